// round 1
// baseline (speedup 1.0000x reference)
#include <cuda_runtime.h>
#include <cstdint>

// Problem constants
#define N_BATCH 64
#define C_IMG   2048   // img channels (conv input channels)
#define S_SP    256    // 16*16 spatial
#define L_TXT   64     // text length
#define C_EMB   1024   // text embed dim / img_embed channels
#define T_INV   0.25f  // 1/temperature

#define SMS 68         // padded smem tile stride (float4-aligned, reduces bank conflicts)

// -------- scratch (device globals: no allocation allowed) --------
// g_tw:   tw [64][64][2048]  (text @ w_img, pre-scaled by 1/T) ; REUSED later as Y [64][2048][64]
// g_lg:   logits [64][64][256] ; becomes attn in-place after softmax
// g_x:    x [64][2048][64] : channels [0,1024)=text^T, [1024,2048)=img_cat
__device__ float g_tw[(size_t)N_BATCH * L_TXT * C_IMG];
__device__ float g_lg[(size_t)N_BATCH * L_TXT * S_SP];
__device__ float g_x [(size_t)N_BATCH * C_IMG * L_TXT];

// =====================================================================
// Shared-memory tile loaders for the 64x64x16 GEMM pattern (256 threads)
// =====================================================================

// transpose-mode: G is [rows][K] row-major (ld), tile 64 rows x 16 k at (r0,k0) -> Sm[k][r]
__device__ __forceinline__ void load_T(const float* __restrict__ G, int ld, int r0, int k0,
                                       float (*Sm)[SMS], int tid) {
    int r  = tid >> 2;           // 0..63
    int kq = (tid & 3) * 4;      // 0,4,8,12
    float4 v = *(const float4*)(G + (size_t)(r0 + r) * ld + k0 + kq);
    Sm[kq + 0][r] = v.x;
    Sm[kq + 1][r] = v.y;
    Sm[kq + 2][r] = v.z;
    Sm[kq + 3][r] = v.w;
}

// direct-mode: G is [K][cols] row-major (ld), tile 16 k x 64 cols at (k0,c0) -> Sm[k][c]
__device__ __forceinline__ void load_D(const float* __restrict__ G, int ld, int k0, int c0,
                                       float (*Sm)[SMS], int tid) {
    int k  = tid >> 4;           // 0..15
    int cq = (tid & 15) * 4;     // 0..60
    *(float4*)&Sm[k][cq] = *(const float4*)(G + (size_t)(k0 + k) * ld + c0 + cq);
}

// 4x4 register-blocked inner product over a 16-deep k-tile
__device__ __forceinline__ void tile_fma(const float (*As)[SMS], const float (*Bs)[SMS],
                                         float acc[4][4], int ty, int tx) {
#pragma unroll
    for (int k = 0; k < 16; k++) {
        float4 a4 = *(const float4*)&As[k][ty * 4];
        float4 b4 = *(const float4*)&Bs[k][tx * 4];
        float av[4] = {a4.x, a4.y, a4.z, a4.w};
        float bv[4] = {b4.x, b4.y, b4.z, b4.w};
#pragma unroll
        for (int i = 0; i < 4; i++)
#pragma unroll
            for (int j = 0; j < 4; j++)
                acc[i][j] += av[i] * bv[j];
    }
}

// =====================================================================
// K0: x[n][c][l] = text[n][l][c]  (c < 1024) -- smem tile transpose
// grid(32, 2, 64) block(32, 8)
// =====================================================================
__global__ void k_text_T(const float* __restrict__ text) {
    __shared__ float tile[32][33];
    int n = blockIdx.z, c0 = blockIdx.x * 32, l0 = blockIdx.y * 32;
    int tx = threadIdx.x, ty = threadIdx.y;
    const float* tp = text + (size_t)n * L_TXT * C_EMB;
#pragma unroll
    for (int j = 0; j < 4; j++)
        tile[ty + j * 8][tx] = tp[(size_t)(l0 + ty + j * 8) * C_EMB + c0 + tx];
    __syncthreads();
    float* xp = g_x + (size_t)n * C_IMG * L_TXT;
#pragma unroll
    for (int j = 0; j < 4; j++)
        xp[(size_t)(c0 + ty + j * 8) * L_TXT + l0 + tx] = tile[tx][ty + j * 8];
}

// =====================================================================
// K1: tw[n][l][c] = (1/T) * sum_o text[n][l][o] * w_img[o][c]
// M=64(l) N=2048(c) K=1024(o); grid(32, 64)
// =====================================================================
__global__ void __launch_bounds__(256) k_tw(const float* __restrict__ text,
                                            const float* __restrict__ w_img) {
    __shared__ float As[16][SMS], Bs[16][SMS];
    int n = blockIdx.y, n0 = blockIdx.x * 64;
    int tid = threadIdx.x, ty = tid >> 4, tx = tid & 15;
    const float* A = text + (size_t)n * L_TXT * C_EMB;
    float acc[4][4] = {};
    for (int k0 = 0; k0 < C_EMB; k0 += 16) {
        load_T(A, C_EMB, 0, k0, As, tid);
        load_D(w_img, C_IMG, k0, n0, Bs, tid);
        __syncthreads();
        tile_fma(As, Bs, acc, ty, tx);
        __syncthreads();
    }
    float* C = g_tw + (size_t)n * L_TXT * C_IMG;
#pragma unroll
    for (int i = 0; i < 4; i++)
#pragma unroll
        for (int j = 0; j < 4; j++)
            C[(size_t)(ty * 4 + i) * C_IMG + n0 + tx * 4 + j] = acc[i][j] * T_INV;
}

// =====================================================================
// K2: logits[n][l][s] = sum_c tw[n][l][c] * img[n][c][s]
// M=64(l) N=256(s) K=2048(c); grid(4, 64)
// =====================================================================
__global__ void __launch_bounds__(256) k_logits(const float* __restrict__ img) {
    __shared__ float As[16][SMS], Bs[16][SMS];
    int n = blockIdx.y, n0 = blockIdx.x * 64;
    int tid = threadIdx.x, ty = tid >> 4, tx = tid & 15;
    const float* A = g_tw + (size_t)n * L_TXT * C_IMG;   // [l][c]
    const float* B = img + (size_t)n * C_IMG * S_SP;     // [c][s]
    float acc[4][4] = {};
    for (int k0 = 0; k0 < C_IMG; k0 += 16) {
        load_T(A, C_IMG, 0, k0, As, tid);
        load_D(B, S_SP, k0, n0, Bs, tid);
        __syncthreads();
        tile_fma(As, Bs, acc, ty, tx);
        __syncthreads();
    }
    float* C = g_lg + (size_t)n * L_TXT * S_SP;
#pragma unroll
    for (int i = 0; i < 4; i++)
#pragma unroll
        for (int j = 0; j < 4; j++)
            C[(size_t)(ty * 4 + i) * S_SP + n0 + tx * 4 + j] = acc[i][j];
}

// =====================================================================
// K3: softmax over s (256), in-place on g_lg AND written to d_out attn region
// one warp per row; grid(512) block(256)
// =====================================================================
__global__ void k_softmax(float* __restrict__ d_attn) {
    int warp = threadIdx.x >> 5, lane = threadIdx.x & 31;
    int row = blockIdx.x * 8 + warp;                 // 0..4095 = n*64+l
    float* lg = g_lg + (size_t)row * S_SP;
    float v[8];
    float m = -1e30f;
#pragma unroll
    for (int j = 0; j < 8; j++) { v[j] = lg[lane + j * 32]; m = fmaxf(m, v[j]); }
#pragma unroll
    for (int o = 16; o; o >>= 1) m = fmaxf(m, __shfl_xor_sync(0xffffffffu, m, o));
    float s = 0.f;
#pragma unroll
    for (int j = 0; j < 8; j++) { v[j] = __expf(v[j] - m); s += v[j]; }
#pragma unroll
    for (int o = 16; o; o >>= 1) s += __shfl_xor_sync(0xffffffffu, s, o);
    float inv = 1.f / s;
#pragma unroll
    for (int j = 0; j < 8; j++) {
        float a = v[j] * inv;
        lg[lane + j * 32] = a;
        d_attn[(size_t)row * S_SP + lane + j * 32] = a;
    }
}

// =====================================================================
// K4: Y[n][c][l] = sum_s img[n][c][s] * attn[n][l][s]   (Y overwrites g_tw)
// M=2048(c) N=64(l) K=256(s); grid(32, 64)
// =====================================================================
__global__ void __launch_bounds__(256) k_Y(const float* __restrict__ img) {
    __shared__ float As[16][SMS], Bs[16][SMS];
    int n = blockIdx.y, m0 = blockIdx.x * 64;
    int tid = threadIdx.x, ty = tid >> 4, tx = tid & 15;
    const float* A = img + (size_t)n * C_IMG * S_SP;     // [c][s]
    const float* B = g_lg + (size_t)n * L_TXT * S_SP;    // attn [l][s] -> B[k=s][l]
    float acc[4][4] = {};
    for (int k0 = 0; k0 < S_SP; k0 += 16) {
        load_T(A, S_SP, m0, k0, As, tid);
        load_T(B, S_SP, 0, k0, Bs, tid);
        __syncthreads();
        tile_fma(As, Bs, acc, ty, tx);
        __syncthreads();
    }
    float* C = g_tw + ((size_t)n * C_IMG + m0) * L_TXT;  // Y
#pragma unroll
    for (int i = 0; i < 4; i++)
#pragma unroll
        for (int j = 0; j < 4; j++)
            C[(size_t)(ty * 4 + i) * L_TXT + tx * 4 + j] = acc[i][j];
}

// =====================================================================
// K5: img_cat[n][m][l] = sum_k w_img[m][k] * Y[n][k][l]  -> g_x channels [1024,2048)
// M=1024 N=64 K=2048; grid(16, 64)
// =====================================================================
__global__ void __launch_bounds__(256) k_imgcat(const float* __restrict__ w_img) {
    __shared__ float As[16][SMS], Bs[16][SMS];
    int n = blockIdx.y, m0 = blockIdx.x * 64;
    int tid = threadIdx.x, ty = tid >> 4, tx = tid & 15;
    const float* B = g_tw + (size_t)n * C_IMG * L_TXT;   // Y [k][l]
    float acc[4][4] = {};
    for (int k0 = 0; k0 < C_IMG; k0 += 16) {
        load_T(w_img, C_IMG, m0, k0, As, tid);
        load_D(B, L_TXT, k0, 0, Bs, tid);
        __syncthreads();
        tile_fma(As, Bs, acc, ty, tx);
        __syncthreads();
    }
    float* C = g_x + ((size_t)n * C_IMG + 1024 + m0) * L_TXT;
#pragma unroll
    for (int i = 0; i < 4; i++)
#pragma unroll
        for (int j = 0; j < 4; j++)
            C[(size_t)(ty * 4 + i) * L_TXT + tx * 4 + j] = acc[i][j];
}

// =====================================================================
// K6: k=1 inception branch (gamma ch 0..511, beta ch 0..511) + fused FiLM epilogue
// out[n][co][l] = (conv1(wg1)+bg1) * img_cat + (conv1(wb1)+bb1)
// grid(8, 64)
// =====================================================================
__global__ void __launch_bounds__(256) k_conv1(const float* __restrict__ wg1,
                                               const float* __restrict__ bg1,
                                               const float* __restrict__ wb1,
                                               const float* __restrict__ bb1,
                                               float* __restrict__ out) {
    __shared__ float Gs[16][SMS], Hs[16][SMS], Xs[16][SMS];
    int n = blockIdx.y, co0 = blockIdx.x * 64;
    int tid = threadIdx.x, ty = tid >> 4, tx = tid & 15;
    const float* xp = g_x + (size_t)n * C_IMG * L_TXT;
    float ga[4][4] = {}, ba[4][4] = {};
    for (int k0 = 0; k0 < C_IMG; k0 += 16) {
        load_T(wg1, C_IMG, co0, k0, Gs, tid);
        load_T(wb1, C_IMG, co0, k0, Hs, tid);
        load_D(xp, L_TXT, k0, 0, Xs, tid);
        __syncthreads();
#pragma unroll
        for (int k = 0; k < 16; k++) {
            float4 g4 = *(const float4*)&Gs[k][ty * 4];
            float4 h4 = *(const float4*)&Hs[k][ty * 4];
            float4 x4 = *(const float4*)&Xs[k][tx * 4];
            float gv[4] = {g4.x, g4.y, g4.z, g4.w};
            float hv[4] = {h4.x, h4.y, h4.z, h4.w};
            float xv[4] = {x4.x, x4.y, x4.z, x4.w};
#pragma unroll
            for (int i = 0; i < 4; i++)
#pragma unroll
                for (int j = 0; j < 4; j++) {
                    ga[i][j] += gv[i] * xv[j];
                    ba[i][j] += hv[i] * xv[j];
                }
        }
        __syncthreads();
    }
    const float* ic = g_x + ((size_t)n * C_IMG + 1024 + co0) * L_TXT;
    float* op = out + ((size_t)n * C_EMB + co0) * L_TXT;
#pragma unroll
    for (int i = 0; i < 4; i++) {
        int r = ty * 4 + i;
        float bgv = bg1[co0 + r], bbv = bb1[co0 + r];
#pragma unroll
        for (int j = 0; j < 4; j++) {
            int l = tx * 4 + j;
            op[(size_t)r * L_TXT + l] =
                (ga[i][j] + bgv) * ic[(size_t)r * L_TXT + l] + (ba[i][j] + bbv);
        }
    }
}

// =====================================================================
// K7: k=3 inception branch (gamma ch 512..1023, beta ch 512..1023) + fused epilogue
// y[o,l] = sum_c sum_t w3[o,c,t] * x[c, l+t-1]  ('same' pad)
// grid(8, 64)
// =====================================================================
__global__ void __launch_bounds__(256) k_conv3(const float* __restrict__ wg3,
                                               const float* __restrict__ bg3,
                                               const float* __restrict__ wb3,
                                               const float* __restrict__ bb3,
                                               float* __restrict__ out) {
    __shared__ float Wg[16][3][SMS], Wb[16][3][SMS];
    __shared__ float Xs[16][72];     // x at cols [4,68); halo zeros at col 3 and 68
    int n = blockIdx.y;
    int wo0 = blockIdx.x * 64;       // weight-row offset in [0,512)
    int co0 = 512 + wo0;             // gamma/beta channel
    int tid = threadIdx.x, ty = tid >> 4, tx = tid & 15;
    const float* xp = g_x + (size_t)n * C_IMG * L_TXT;
    if (tid < 16) { Xs[tid][3] = 0.f; Xs[tid][68] = 0.f; }
    float ga[4][4] = {}, ba[4][4] = {};
    for (int k0 = 0; k0 < C_IMG; k0 += 16) {
        // weight tiles: w3[(o)*2048 + c][t] -> W[c][t][o]
        for (int i = tid; i < 64 * 48; i += 256) {
            int o = i / 48, r = i % 48, c = r / 3, t = r % 3;
            size_t gidx = ((size_t)(wo0 + o) * C_IMG + (k0 + c)) * 3 + t;
            Wg[c][t][o] = wg3[gidx];
            Wb[c][t][o] = wb3[gidx];
        }
        {   // x tile
            int kk = tid >> 4, l4 = (tid & 15) * 4;
            *(float4*)&Xs[kk][4 + l4] = *(const float4*)(xp + (size_t)(k0 + kk) * L_TXT + l4);
        }
        __syncthreads();
#pragma unroll
        for (int k = 0; k < 16; k++) {
            float x6[6];
            float4 xm = *(const float4*)&Xs[k][4 + tx * 4];
            x6[0] = Xs[k][3 + tx * 4];
            x6[1] = xm.x; x6[2] = xm.y; x6[3] = xm.z; x6[4] = xm.w;
            x6[5] = Xs[k][8 + tx * 4];
#pragma unroll
            for (int t = 0; t < 3; t++) {
                float4 g4 = *(const float4*)&Wg[k][t][ty * 4];
                float4 h4 = *(const float4*)&Wb[k][t][ty * 4];
                float gv[4] = {g4.x, g4.y, g4.z, g4.w};
                float hv[4] = {h4.x, h4.y, h4.z, h4.w};
#pragma unroll
                for (int i = 0; i < 4; i++)
#pragma unroll
                    for (int j = 0; j < 4; j++) {
                        ga[i][j] += gv[i] * x6[j + t];
                        ba[i][j] += hv[i] * x6[j + t];
                    }
            }
        }
        __syncthreads();
    }
    const float* ic = g_x + ((size_t)n * C_IMG + 1024 + co0) * L_TXT;
    float* op = out + ((size_t)n * C_EMB + co0) * L_TXT;
#pragma unroll
    for (int i = 0; i < 4; i++) {
        int r = ty * 4 + i;
        float bgv = bg3[wo0 + r], bbv = bb3[wo0 + r];
#pragma unroll
        for (int j = 0; j < 4; j++) {
            int l = tx * 4 + j;
            op[(size_t)r * L_TXT + l] =
                (ga[i][j] + bgv) * ic[(size_t)r * L_TXT + l] + (ba[i][j] + bbv);
        }
    }
}

// =====================================================================
extern "C" void kernel_launch(void* const* d_in, const int* in_sizes, int n_in,
                              void* d_out, int out_size) {
    const float* img   = (const float*)d_in[0];   // [64,2048,16,16]
    const float* text  = (const float*)d_in[1];   // [64,64,1024]
    const float* w_img = (const float*)d_in[2];   // [1024,2048]
    const float* wg1   = (const float*)d_in[3];   // [512,2048,1]
    const float* bg1   = (const float*)d_in[4];
    const float* wg3   = (const float*)d_in[5];   // [512,2048,3]
    const float* bg3   = (const float*)d_in[6];
    const float* wb1   = (const float*)d_in[7];
    const float* bb1   = (const float*)d_in[8];
    const float* wb3   = (const float*)d_in[9];
    const float* bb3   = (const float*)d_in[10];

    float* out = (float*)d_out;                                   // [64,1024,64]
    float* attn_out = out + (size_t)N_BATCH * C_EMB * L_TXT;      // [64,64,256]

    k_text_T <<<dim3(32, 2, 64), dim3(32, 8)>>>(text);
    k_tw     <<<dim3(32, 64), 256>>>(text, w_img);
    k_logits <<<dim3(4, 64), 256>>>(img);
    k_softmax<<<512, 256>>>(attn_out);
    k_Y      <<<dim3(32, 64), 256>>>(img);
    k_imgcat <<<dim3(16, 64), 256>>>(w_img);
    k_conv1  <<<dim3(8, 64), 256>>>(wg1, bg1, wb1, bb1, out);
    k_conv3  <<<dim3(8, 64), 256>>>(wg3, bg3, wb3, bb3, out);
}

// round 4
// speedup vs baseline: 2.8335x; 2.8335x over previous
#include <cuda_runtime.h>
#include <cuda_fp16.h>
#include <cstdint>

typedef __half H;

// ---------------- problem constants ----------------
#define T_INV 0.25f
#define WSCALE 64.0f      // weight pre-scale (power of 2, exact)
#define WINV (1.0f / 64.0f)

// ---------------- device scratch (no allocs allowed) ----------------
// K-major fp16 hi/lo operand arrays
__device__ __align__(16) H d_xth[4096L * 2048];   // x^T rows (n,l), cols c (0-1023 text, 1024+ img_cat)
__device__ __align__(16) H d_xtl[4096L * 2048];
__device__ __align__(16) H d_wTh[2048L * 1024];   // w_img^T [c][o] (x64)
__device__ __align__(16) H d_wTl[2048L * 1024];
__device__ __align__(16) H d_wih[1024L * 2048];   // w_img [o][c] (x64)
__device__ __align__(16) H d_wil[1024L * 2048];
__device__ __align__(16) H d_w1h[1024L * 2048];   // stacked [gamma;beta] k=1 weights (x64)
__device__ __align__(16) H d_w1l[1024L * 2048];
__device__ __align__(16) H d_w3h[1024L * 6144];   // stacked k=3 weights (x64)
__device__ __align__(16) H d_w3l[1024L * 6144];
__device__ __align__(16) H d_twh[4096L * 2048];   // tw rows (n,l), cols c
__device__ __align__(16) H d_twl[4096L * 2048];
__device__ __align__(16) H d_imh[64L * 2048 * 256];  // img [n][c][s]
__device__ __align__(16) H d_iml[64L * 2048 * 256];
__device__ __align__(16) H d_iTh[64L * 256 * 2048];  // img^T [n][s][c]
__device__ __align__(16) H d_iTl[64L * 256 * 2048];
__device__ __align__(16) H d_ath[4096L * 256];    // attn rows (n,l), cols s
__device__ __align__(16) H d_atl[4096L * 256];
__device__ __align__(16) H d_yth[4096L * 2048];   // Y^T rows (n,l), cols c
__device__ __align__(16) H d_ytl[4096L * 2048];
__device__ __align__(16) H d_x3h[4096L * 6144];   // im2col rows (n,l), cols c*3+t
__device__ __align__(16) H d_x3l[4096L * 6144];
// fp32 scratch
__device__ float g_lg [64L * 64 * 256];    // logits
__device__ float g_ic [1024L * 4096];      // img_cat [o][(n,l)]
__device__ float g_gb1[1024L * 4096];      // conv1 raw out [gamma512;beta512][(n,l)]
__device__ float g_gb3[1024L * 4096];      // conv3 raw out

// ---------------- helpers ----------------
__device__ __forceinline__ void hsplit(float v, H& h, H& l) {
    h = __float2half_rn(v);
    l = __float2half_rn(v - __half2float(h));
}

__device__ __forceinline__ void ldm4(uint32_t* r, uint32_t a) {
    asm volatile("ldmatrix.sync.aligned.m8n8.x4.shared.b16 {%0,%1,%2,%3}, [%4];"
                 : "=r"(r[0]), "=r"(r[1]), "=r"(r[2]), "=r"(r[3]) : "r"(a));
}
__device__ __forceinline__ void mma16816(float* c, const uint32_t* a, uint32_t b0, uint32_t b1) {
    asm volatile("mma.sync.aligned.m16n8k16.row.col.f32.f16.f16.f32 "
                 "{%0,%1,%2,%3},{%4,%5,%6,%7},{%8,%9},{%0,%1,%2,%3};"
                 : "+f"(c[0]), "+f"(c[1]), "+f"(c[2]), "+f"(c[3])
                 : "r"(a[0]), "r"(a[1]), "r"(a[2]), "r"(a[3]), "r"(b0), "r"(b1));
}
__device__ __forceinline__ void cpa16(uint32_t dst, const void* src) {
    asm volatile("cp.async.cg.shared.global [%0], [%1], 16;" :: "r"(dst), "l"(src));
}

// =====================================================================
// Generic 3-chain split-fp16 GEMM: C[M,N] = A[M,K] * B[N,K]^T
// A = Ah+Al, B = Bh+Bl; acc = AhBh + AhBl + AlBh (fp32)
// BM x BN block tile, BK=32, warp tile 32x32, 2-stage cp.async pipeline
// =====================================================================
template<int BM, int BN>
__global__ void __launch_bounds__((BM / 32) * (BN / 32) * 32)
k_gemm(const H* __restrict__ Ah, const H* __restrict__ Al, long aB,
       const H* __restrict__ Bh, const H* __restrict__ Bl, long bB,
       int K, int lda, int ldb, int ep, float scale,
       float* __restrict__ fp0, H* __restrict__ hp0, H* __restrict__ hp1) {
    constexpr int NW = (BM / 32) * (BN / 32);
    constexpr int NT = NW * 32;
    constexpr int RS = 40;                        // smem row stride (halves)
    constexpr int ASZ = BM * RS, BSZ = BN * RS;   // halves
    constexpr int STGB = (2 * ASZ + 2 * BSZ) * 2; // bytes per stage

    extern __shared__ H sm[];
    const int tid = threadIdx.x, lane = tid & 31, warp = tid >> 5;
    const int wc = warp % (BN / 32), wr = warp / (BN / 32);
    const int z = blockIdx.z;
    Ah += (long)z * aB; Al += (long)z * aB;
    Bh += (long)z * bB; Bl += (long)z * bB;
    const long am0 = (long)blockIdx.y * BM, bn0 = (long)blockIdx.x * BN;

    const uint32_t smb = (uint32_t)__cvta_generic_to_shared(sm);

    // ldmatrix per-lane source coords (within tile)
    const int aRow = wr * 32 + ((lane >> 3) & 1) * 8 + (lane & 7);
    const int aK   = (lane >> 4) * 8;
    const int bRow = wc * 32 + (lane >> 4) * 8 + (lane & 7);
    const int bK   = ((lane >> 3) & 1) * 8;

    float acc[2][4][4];
#pragma unroll
    for (int a = 0; a < 2; a++)
#pragma unroll
        for (int b = 0; b < 4; b++)
#pragma unroll
            for (int c = 0; c < 4; c++) acc[a][b][c] = 0.f;

    const int KT = K / 32;

#define LOAD_STAGE(S, KT_IDX)                                                        \
    {                                                                                \
        const uint32_t st = smb + (uint32_t)(S) * STGB;                              \
        const int k0 = (KT_IDX) * 32;                                                \
        for (int ch = tid; ch < BM * 4; ch += NT) {                                  \
            int row = ch >> 2, sg = ch & 3;                                          \
            uint32_t d = st + (uint32_t)(row * RS + sg * 8) * 2;                     \
            long go = (am0 + row) * (long)lda + k0 + sg * 8;                         \
            cpa16(d, Ah + go);                                                       \
            cpa16(d + ASZ * 2, Al + go);                                             \
        }                                                                            \
        for (int ch = tid; ch < BN * 4; ch += NT) {                                  \
            int row = ch >> 2, sg = ch & 3;                                          \
            uint32_t d = st + (uint32_t)(2 * ASZ * 2) + (uint32_t)(row * RS + sg * 8) * 2; \
            long go = (bn0 + row) * (long)ldb + k0 + sg * 8;                         \
            cpa16(d, Bh + go);                                                       \
            cpa16(d + BSZ * 2, Bl + go);                                             \
        }                                                                            \
        asm volatile("cp.async.commit_group;" ::: "memory");                         \
    }

    LOAD_STAGE(0, 0);

    for (int kt = 0; kt < KT; kt++) {
        if (kt + 1 < KT) {
            LOAD_STAGE((kt + 1) & 1, kt + 1);
            asm volatile("cp.async.wait_group 1;" ::: "memory");
        } else {
            asm volatile("cp.async.wait_group 0;" ::: "memory");
        }
        __syncthreads();

        const uint32_t st = smb + (uint32_t)(kt & 1) * STGB;
        const uint32_t aH0 = st, aL0 = st + ASZ * 2;
        const uint32_t bH0 = st + 2 * ASZ * 2, bL0 = st + 2 * ASZ * 2 + BSZ * 2;
#pragma unroll
        for (int chn = 0; chn < 3; chn++) {
            const uint32_t ab = (chn == 2) ? aL0 : aH0;
            const uint32_t bb = (chn == 1) ? bL0 : bH0;
#pragma unroll
            for (int kk = 0; kk < 32; kk += 16) {
                uint32_t af[2][4], bf[2][4];
#pragma unroll
                for (int mi = 0; mi < 2; mi++)
                    ldm4(af[mi], ab + (uint32_t)((aRow + mi * 16) * RS + aK + kk) * 2);
#pragma unroll
                for (int nj = 0; nj < 2; nj++)
                    ldm4(bf[nj], bb + (uint32_t)((bRow + nj * 16) * RS + bK + kk) * 2);
#pragma unroll
                for (int mi = 0; mi < 2; mi++)
#pragma unroll
                    for (int ni = 0; ni < 4; ni++)
                        mma16816(acc[mi][ni], af[mi], bf[ni >> 1][(ni & 1) * 2],
                                 bf[ni >> 1][(ni & 1) * 2 + 1]);
            }
        }
        __syncthreads();
    }
#undef LOAD_STAGE

    // ---------------- epilogue ----------------
    const int gr0 = (int)am0 + wr * 32 + (lane >> 2);
    const int gc0 = (int)bn0 + wc * 32 + (lane & 3) * 2;
#pragma unroll
    for (int mi = 0; mi < 2; mi++)
#pragma unroll
        for (int ni = 0; ni < 4; ni++) {
            const float* c = acc[mi][ni];
            const int col = gc0 + ni * 8;
#pragma unroll
            for (int hh = 0; hh < 2; hh++) {
                const int row = gr0 + mi * 16 + hh * 8;
                float v0 = c[hh * 2 + 0] * scale, v1 = c[hh * 2 + 1] * scale;
                if (ep == 0 || ep == 2) {          // split-store h/l, ld 2048
                    int r = (ep == 2) ? z * 64 + row : row;
                    long o = (long)r * 2048 + col;
                    H h0, l0, h1, l1;
                    hsplit(v0, h0, l0); hsplit(v1, h1, l1);
                    *(__half2*)(hp0 + o) = __halves2half2(h0, h1);
                    *(__half2*)(hp1 + o) = __halves2half2(l0, l1);
                } else if (ep == 1) {              // logits fp32 [z][l][s]
                    long o = (long)z * 16384 + (long)row * 256 + col;
                    float2 v = {v0, v1};
                    *(float2*)(fp0 + o) = v;
                } else if (ep == 3) {              // img_cat: fp32 ic + xT h/l scatter
                    long o = (long)row * 4096 + col;
                    float2 v = {v0, v1};
                    *(float2*)(fp0 + o) = v;
                    H h0, l0, h1, l1;
                    hsplit(v0, h0, l0); hsplit(v1, h1, l1);
                    hp0[(long)col * 2048 + 1024 + row] = h0;
                    hp1[(long)col * 2048 + 1024 + row] = l0;
                    hp0[(long)(col + 1) * 2048 + 1024 + row] = h1;
                    hp1[(long)(col + 1) * 2048 + 1024 + row] = l1;
                } else {                           // ep 4: conv gb fp32
                    long o = (long)row * 4096 + col;
                    float2 v = {v0, v1};
                    *(float2*)(fp0 + o) = v;
                }
            }
        }
}

// =====================================================================
// prep kernels
// =====================================================================
__global__ void p_text(const float* __restrict__ t) {
    for (long i = (long)blockIdx.x * blockDim.x + threadIdx.x; i < 64L * 64 * 1024;
         i += (long)gridDim.x * blockDim.x) {
        long row = i >> 10; int c = (int)(i & 1023);
        H h, l; hsplit(t[i], h, l);
        d_xth[row * 2048 + c] = h; d_xtl[row * 2048 + c] = l;
    }
}

// w_img: native split (x64) + transposed split (x64)
__global__ void p_w(const float* __restrict__ w) {
    __shared__ float t[32][33];
    int o0 = blockIdx.y * 32, c0 = blockIdx.x * 32;
    int tx = threadIdx.x, ty = threadIdx.y;
#pragma unroll
    for (int j = 0; j < 4; j++) {
        int o = o0 + ty + j * 8;
        float v = w[(long)o * 2048 + c0 + tx] * WSCALE;
        H h, l; hsplit(v, h, l);
        d_wih[(long)o * 2048 + c0 + tx] = h;
        d_wil[(long)o * 2048 + c0 + tx] = l;
        t[ty + j * 8][tx] = v;
    }
    __syncthreads();
#pragma unroll
    for (int j = 0; j < 4; j++) {
        int c = c0 + ty + j * 8;
        float v = t[tx][ty + j * 8];
        H h, l; hsplit(v, h, l);
        d_wTh[(long)c * 1024 + o0 + tx] = h;
        d_wTl[(long)c * 1024 + o0 + tx] = l;
    }
}

__global__ void p_img(const float* __restrict__ img) {
    __shared__ float t[32][33];
    int n = blockIdx.z, c0 = blockIdx.y * 32, s0 = blockIdx.x * 32;
    int tx = threadIdx.x, ty = threadIdx.y;
    const float* ip = img + (long)n * 2048 * 256;
#pragma unroll
    for (int j = 0; j < 4; j++) {
        int c = c0 + ty + j * 8;
        float v = ip[(long)c * 256 + s0 + tx];
        H h, l; hsplit(v, h, l);
        long o = (long)n * 524288 + (long)c * 256 + s0 + tx;
        d_imh[o] = h; d_iml[o] = l;
        t[ty + j * 8][tx] = v;
    }
    __syncthreads();
#pragma unroll
    for (int j = 0; j < 4; j++) {
        int s = s0 + ty + j * 8;
        float v = t[tx][ty + j * 8];
        H h, l; hsplit(v, h, l);
        long o = (long)n * 524288 + (long)s * 2048 + c0 + tx;
        d_iTh[o] = h; d_iTl[o] = l;
    }
}

__global__ void p_w1(const float* __restrict__ wg1, const float* __restrict__ wb1) {
    for (long i = (long)blockIdx.x * blockDim.x + threadIdx.x; i < 1024L * 2048;
         i += (long)gridDim.x * blockDim.x) {
        float v = ((i < 512L * 2048) ? wg1[i] : wb1[i - 512L * 2048]) * WSCALE;
        hsplit(v, d_w1h[i], d_w1l[i]);
    }
}
__global__ void p_w3(const float* __restrict__ wg3, const float* __restrict__ wb3) {
    int row = blockIdx.x;
    const float* src = (row < 512) ? wg3 + (long)row * 6144 : wb3 + (long)(row - 512) * 6144;
    for (int c = threadIdx.x; c < 6144; c += 256) {
        float v = src[c] * WSCALE;
        hsplit(v, d_w3h[(long)row * 6144 + c], d_w3l[(long)row * 6144 + c]);
    }
}

__global__ void p_x3() {
    int row = blockIdx.x;                  // (n,l)
    int n = row >> 6, l = row & 63;
    for (int c = threadIdx.x; c < 2048; c += 256) {
#pragma unroll
        for (int t = 0; t < 3; t++) {
            int sl = l + t - 1;
            H vh = __float2half_rn(0.f), vl = vh;
            if (sl >= 0 && sl < 64) {
                long o = ((long)(n << 6) + sl) * 2048 + c;
                vh = d_xth[o]; vl = d_xtl[o];
            }
            long d = (long)row * 6144 + (long)c * 3 + t;
            d_x3h[d] = vh; d_x3l[d] = vl;
        }
    }
}

__global__ void k_softmax(float* __restrict__ d_attn) {
    int warp = threadIdx.x >> 5, lane = threadIdx.x & 31;
    int row = blockIdx.x * 8 + warp;
    float* lg = g_lg + (long)row * 256;
    float v[8];
    float m = -1e30f;
#pragma unroll
    for (int j = 0; j < 8; j++) { v[j] = lg[lane + j * 32]; m = fmaxf(m, v[j]); }
#pragma unroll
    for (int o = 16; o; o >>= 1) m = fmaxf(m, __shfl_xor_sync(0xffffffffu, m, o));
    float s = 0.f;
#pragma unroll
    for (int j = 0; j < 8; j++) { v[j] = __expf(v[j] - m); s += v[j]; }
#pragma unroll
    for (int o = 16; o; o >>= 1) s += __shfl_xor_sync(0xffffffffu, s, o);
    float inv = 1.f / s;
#pragma unroll
    for (int j = 0; j < 8; j++) {
        float a = v[j] * inv;
        int idx = lane + j * 32;
        d_attn[(long)row * 256 + idx] = a;
        H h, l; hsplit(a, h, l);
        d_ath[(long)row * 256 + idx] = h;
        d_atl[(long)row * 256 + idx] = l;
    }
}

__global__ void k_film(const float* __restrict__ bg1, const float* __restrict__ bb1,
                       const float* __restrict__ bg3, const float* __restrict__ bb3,
                       float* __restrict__ out) {
    for (long idx = (long)blockIdx.x * blockDim.x + threadIdx.x; idx < 64L * 1024 * 64;
         idx += (long)gridDim.x * blockDim.x) {
        int l = (int)(idx & 63), co = (int)((idx >> 6) & 1023), n = (int)(idx >> 16);
        long cnl = (long)(n << 6) + l;
        float g, b;
        if (co < 512) {
            g = g_gb1[(long)co * 4096 + cnl] + bg1[co];
            b = g_gb1[(long)(co + 512) * 4096 + cnl] + bb1[co];
        } else {
            int c2 = co - 512;
            g = g_gb3[(long)c2 * 4096 + cnl] + bg3[c2];
            b = g_gb3[(long)(c2 + 512) * 4096 + cnl] + bb3[c2];
        }
        out[idx] = g * g_ic[(long)co * 4096 + cnl] + b;
    }
}

// =====================================================================
extern "C" void kernel_launch(void* const* d_in, const int* in_sizes, int n_in,
                              void* d_out, int out_size) {
    const float* img   = (const float*)d_in[0];
    const float* text  = (const float*)d_in[1];
    const float* w_img = (const float*)d_in[2];
    const float* wg1   = (const float*)d_in[3];
    const float* bg1   = (const float*)d_in[4];
    const float* wg3   = (const float*)d_in[5];
    const float* bg3   = (const float*)d_in[6];
    const float* wb1   = (const float*)d_in[7];
    const float* bb1   = (const float*)d_in[8];
    const float* wb3   = (const float*)d_in[9];
    const float* bb3   = (const float*)d_in[10];

    float* out = (float*)d_out;                               // [64,1024,64]
    float* attn_out = out + 64L * 1024 * 64;                  // [64,64,256]

    // symbol addresses
    H *xth, *xtl, *wTh, *wTl, *wih, *wil, *w1h, *w1l, *w3h, *w3l;
    H *twh, *twl, *imh, *iml, *iTh, *iTl, *ath, *atl, *yth, *ytl, *x3h, *x3l;
    float *lg, *ic, *gb1, *gb3;
    cudaGetSymbolAddress((void**)&xth, d_xth);  cudaGetSymbolAddress((void**)&xtl, d_xtl);
    cudaGetSymbolAddress((void**)&wTh, d_wTh);  cudaGetSymbolAddress((void**)&wTl, d_wTl);
    cudaGetSymbolAddress((void**)&wih, d_wih);  cudaGetSymbolAddress((void**)&wil, d_wil);
    cudaGetSymbolAddress((void**)&w1h, d_w1h);  cudaGetSymbolAddress((void**)&w1l, d_w1l);
    cudaGetSymbolAddress((void**)&w3h, d_w3h);  cudaGetSymbolAddress((void**)&w3l, d_w3l);
    cudaGetSymbolAddress((void**)&twh, d_twh);  cudaGetSymbolAddress((void**)&twl, d_twl);
    cudaGetSymbolAddress((void**)&imh, d_imh);  cudaGetSymbolAddress((void**)&iml, d_iml);
    cudaGetSymbolAddress((void**)&iTh, d_iTh);  cudaGetSymbolAddress((void**)&iTl, d_iTl);
    cudaGetSymbolAddress((void**)&ath, d_ath);  cudaGetSymbolAddress((void**)&atl, d_atl);
    cudaGetSymbolAddress((void**)&yth, d_yth);  cudaGetSymbolAddress((void**)&ytl, d_ytl);
    cudaGetSymbolAddress((void**)&x3h, d_x3h);  cudaGetSymbolAddress((void**)&x3l, d_x3l);
    cudaGetSymbolAddress((void**)&lg, g_lg);    cudaGetSymbolAddress((void**)&ic, g_ic);
    cudaGetSymbolAddress((void**)&gb1, g_gb1);  cudaGetSymbolAddress((void**)&gb3, g_gb3);

    const int SM_BIG = (2 * 128 * 40 + 2 * 64 * 40) * 2 * 2;  // 61440 B
    const int SM_SML = (2 * 64 * 40 + 2 * 64 * 40) * 2 * 2;   // 40960 B
    cudaFuncSetAttribute(k_gemm<128, 64>, cudaFuncAttributeMaxDynamicSharedMemorySize, SM_BIG);
    cudaFuncSetAttribute(k_gemm<64, 64>, cudaFuncAttributeMaxDynamicSharedMemorySize, SM_SML);

    // ---- preps (independent) ----
    p_text<<<2048, 256>>>(text);
    p_w   <<<dim3(64, 32), dim3(32, 8)>>>(w_img);
    p_img <<<dim3(8, 64, 64), dim3(32, 8)>>>(img);
    p_w1  <<<2048, 256>>>(wg1, wb1);
    p_w3  <<<1024, 256>>>(wg3, wb3);

    // ---- tw: M=4096 N=2048 K=1024 ; ep0 (scale T_INV/WSCALE) ----
    k_gemm<128, 64><<<dim3(32, 32, 1), 256, SM_BIG>>>(
        xth, xtl, 0, wTh, wTl, 0, 1024, 2048, 1024, 0, T_INV * WINV, nullptr, twh, twl);

    // ---- logits: batched M=64 N=256 K=2048 ; ep1 ----
    k_gemm<64, 64><<<dim3(4, 1, 64), 128, SM_SML>>>(
        twh, twl, 64L * 2048, iTh, iTl, 256L * 2048, 2048, 2048, 2048, 1, 1.0f, lg, nullptr, nullptr);

    k_softmax<<<512, 256>>>(attn_out);

    // ---- Yt: batched M=64 N=2048 K=256 ; ep2 ----
    k_gemm<64, 64><<<dim3(32, 1, 64), 128, SM_SML>>>(
        ath, atl, 64L * 256, imh, iml, 2048L * 256, 256, 256, 256, 2, 1.0f, nullptr, yth, ytl);

    // ---- img_cat: M=1024 N=4096 K=2048 ; ep3 (scale 1/WSCALE) ----
    k_gemm<128, 64><<<dim3(64, 8, 1), 256, SM_BIG>>>(
        wih, wil, 0, yth, ytl, 0, 2048, 2048, 2048, 3, WINV, ic, xth, xtl);

    p_x3<<<4096, 256>>>();

    // ---- conv1: M=1024 N=4096 K=2048 ; ep4 ----
    k_gemm<128, 64><<<dim3(64, 8, 1), 256, SM_BIG>>>(
        w1h, w1l, 0, xth, xtl, 0, 2048, 2048, 2048, 4, WINV, gb1, nullptr, nullptr);

    // ---- conv3: M=1024 N=4096 K=6144 ; ep4 ----
    k_gemm<128, 64><<<dim3(64, 8, 1), 256, SM_BIG>>>(
        w3h, w3l, 0, x3h, x3l, 0, 6144, 6144, 6144, 4, WINV, gb3, nullptr, nullptr);

    k_film<<<4096, 256>>>(bg1, bb1, bg3, bb3, out);
}

// round 6
// speedup vs baseline: 3.4028x; 1.2009x over previous
#include <cuda_runtime.h>
#include <cuda_fp16.h>
#include <cstdint>

typedef __half H;

#define T_INV 0.25f
#define WSCALE 64.0f
#define WINV (1.0f / 64.0f)

// ---------------- device scratch ----------------
__device__ __align__(16) H d_xth[4096L * 2048];   // x^T rows (n,l), cols c
__device__ __align__(16) H d_xtl[4096L * 2048];   // lo: text cols only (tw A-side)
__device__ __align__(16) H d_wTh[2048L * 1024];   // w_img^T [c][o] (x64)
__device__ __align__(16) H d_wTl[2048L * 1024];
__device__ __align__(16) H d_wih[1024L * 2048];   // w_img [o][c] (x64)
__device__ __align__(16) H d_wil[1024L * 2048];
__device__ __align__(16) H d_w1h[1024L * 2048];   // stacked [gamma;beta] k=1 (x64)
__device__ __align__(16) H d_w1l[1024L * 2048];
__device__ __align__(16) H d_w3h[1024L * 6144];   // stacked k=3 (x64)
__device__ __align__(16) H d_w3l[1024L * 6144];
__device__ __align__(16) H d_twh[4096L * 2048];   // tw rows (n,l), cols c
__device__ __align__(16) H d_twl[4096L * 2048];
__device__ __align__(16) H d_imh[64L * 2048 * 256];  // img [n][c][s] (hi only)
__device__ __align__(16) H d_iTh[64L * 256 * 2048];  // img^T [n][s][c]
__device__ __align__(16) H d_iTl[64L * 256 * 2048];
__device__ __align__(16) H d_ath[4096L * 256];    // attn rows (n,l), cols s
__device__ __align__(16) H d_atl[4096L * 256];
__device__ __align__(16) H d_yth[4096L * 2048];   // Y^T rows (n,l), cols c (hi only)
__device__ __align__(16) H d_x3h[4096L * 6144];   // im2col rows (n,l) (hi only)
// fp32 scratch
__device__ float g_lg [64L * 64 * 256];
__device__ float g_ic [1024L * 4096];
__device__ float g_gb1[1024L * 4096];
__device__ float g_gb3[1024L * 4096];

// ---------------- helpers ----------------
__device__ __forceinline__ void hsplit(float v, H& h, H& l) {
    h = __float2half_rn(v);
    l = __float2half_rn(v - __half2float(h));
}
__device__ __forceinline__ void ldm4(uint32_t* r, uint32_t a) {
    asm volatile("ldmatrix.sync.aligned.m8n8.x4.shared.b16 {%0,%1,%2,%3}, [%4];"
                 : "=r"(r[0]), "=r"(r[1]), "=r"(r[2]), "=r"(r[3]) : "r"(a));
}
__device__ __forceinline__ void mma16816(float* c, const uint32_t* a, uint32_t b0, uint32_t b1) {
    asm volatile("mma.sync.aligned.m16n8k16.row.col.f32.f16.f16.f32 "
                 "{%0,%1,%2,%3},{%4,%5,%6,%7},{%8,%9},{%0,%1,%2,%3};"
                 : "+f"(c[0]), "+f"(c[1]), "+f"(c[2]), "+f"(c[3])
                 : "r"(a[0]), "r"(a[1]), "r"(a[2]), "r"(a[3]), "r"(b0), "r"(b1));
}
__device__ __forceinline__ void cpa16(uint32_t dst, const void* src) {
    asm volatile("cp.async.cg.shared.global [%0], [%1], 16;" :: "r"(dst), "l"(src));
}

// =====================================================================
// Split-fp16 GEMM: C[M,N] = A[M,K] * B[N,K]^T, fp32 accum
// NCH=3: AhBh + AlBh + AhBl (both operands ~fp32-exact)
// NCH=2: AhBh + AlBh       (A exact, B fp16-quantized; Bl not loaded)
// BK=32, 3-stage cp.async, warp tile 32x(WN), WN=64 when BN>=128
// =====================================================================
template<int BM, int BN, int NCH>
__global__ void __launch_bounds__((BM / 32) * (BN / ((BN >= 128) ? 64 : 32)) * 32)
k_gemm(const H* __restrict__ Ah, const H* __restrict__ Al, long aB,
       const H* __restrict__ Bh, const H* __restrict__ Bl, long bB,
       int K, int lda, int ldb, int ep, float scale,
       float* __restrict__ fp0, H* __restrict__ hp0, H* __restrict__ hp1) {
    constexpr int WN = (BN >= 128) ? 64 : 32;
    constexpr int NWC = BN / WN, NWR = BM / 32, NW = NWC * NWR, NT = NW * 32;
    constexpr int NI = WN / 8;      // mma col-tiles per warp
    constexpr int NJ = WN / 16;     // B ldmatrix fragments per warp
    constexpr int RS = 40;          // smem row stride (halves)
    constexpr int ASZ = BM * RS, BSZ = BN * RS;          // halves
    constexpr int STGB = (2 * ASZ + (NCH == 3 ? 2 : 1) * BSZ) * 2;  // bytes

    extern __shared__ H sm[];
    const int tid = threadIdx.x, lane = tid & 31, warp = tid >> 5;
    const int wc = warp % NWC, wr = warp / NWC;
    const int z = blockIdx.z;
    Ah += (long)z * aB; Al += (long)z * aB;
    Bh += (long)z * bB; if (NCH == 3) Bl += (long)z * bB;
    const long am0 = (long)blockIdx.y * BM, bn0 = (long)blockIdx.x * BN;

    const uint32_t smb = (uint32_t)__cvta_generic_to_shared(sm);

    const int aRow = wr * 32 + ((lane >> 3) & 1) * 8 + (lane & 7);
    const int aK   = (lane >> 4) * 8;
    const int bRow = wc * WN + (lane >> 4) * 8 + (lane & 7);
    const int bK   = ((lane >> 3) & 1) * 8;

    float acc[2][NI][4];
#pragma unroll
    for (int a = 0; a < 2; a++)
#pragma unroll
        for (int b = 0; b < NI; b++)
#pragma unroll
            for (int c = 0; c < 4; c++) acc[a][b][c] = 0.f;

    const int KT = K / 32;

#define LOAD_STAGE(S, KT_IDX)                                                          \
    {                                                                                  \
        const uint32_t st = smb + (uint32_t)(S) * STGB;                                \
        const int k0 = (KT_IDX) * 32;                                                  \
        for (int ch = tid; ch < BM * 4; ch += NT) {                                    \
            int row = ch >> 2, sg = ch & 3;                                            \
            uint32_t d = st + (uint32_t)(row * RS + sg * 8) * 2;                       \
            long go = (am0 + row) * (long)lda + k0 + sg * 8;                           \
            cpa16(d, Ah + go);                                                         \
            cpa16(d + ASZ * 2, Al + go);                                               \
        }                                                                              \
        for (int ch = tid; ch < BN * 4; ch += NT) {                                    \
            int row = ch >> 2, sg = ch & 3;                                            \
            uint32_t d = st + (uint32_t)(2 * ASZ * 2) + (uint32_t)(row * RS + sg * 8) * 2; \
            long go = (bn0 + row) * (long)ldb + k0 + sg * 8;                           \
            cpa16(d, Bh + go);                                                         \
            if (NCH == 3) cpa16(d + BSZ * 2, Bl + go);                                 \
        }                                                                              \
        asm volatile("cp.async.commit_group;" ::: "memory");                           \
    }

    LOAD_STAGE(0, 0);
    if (KT > 1) LOAD_STAGE(1, 1);

    for (int kt = 0; kt < KT; kt++) {
        if (kt + 2 < KT) LOAD_STAGE((kt + 2) % 3, kt + 2);
        const int rem = KT - 1 - kt;
        if (rem >= 2)      asm volatile("cp.async.wait_group 2;" ::: "memory");
        else if (rem == 1) asm volatile("cp.async.wait_group 1;" ::: "memory");
        else               asm volatile("cp.async.wait_group 0;" ::: "memory");
        __syncthreads();

        const uint32_t st = smb + (uint32_t)(kt % 3) * STGB;
        const uint32_t aH0 = st, aL0 = st + ASZ * 2;
        const uint32_t bH0 = st + 2 * ASZ * 2, bL0 = bH0 + BSZ * 2;
#pragma unroll
        for (int kk = 0; kk < 32; kk += 16) {
            uint32_t bf[NJ][4], afh[2][4], afl[2][4];
#pragma unroll
            for (int nj = 0; nj < NJ; nj++)
                ldm4(bf[nj], bH0 + (uint32_t)((bRow + nj * 16) * RS + bK + kk) * 2);
#pragma unroll
            for (int mi = 0; mi < 2; mi++)
                ldm4(afh[mi], aH0 + (uint32_t)((aRow + mi * 16) * RS + aK + kk) * 2);
#pragma unroll
            for (int mi = 0; mi < 2; mi++)
#pragma unroll
                for (int ni = 0; ni < NI; ni++)
                    mma16816(acc[mi][ni], afh[mi], bf[ni >> 1][(ni & 1) * 2],
                             bf[ni >> 1][(ni & 1) * 2 + 1]);
#pragma unroll
            for (int mi = 0; mi < 2; mi++)
                ldm4(afl[mi], aL0 + (uint32_t)((aRow + mi * 16) * RS + aK + kk) * 2);
#pragma unroll
            for (int mi = 0; mi < 2; mi++)
#pragma unroll
                for (int ni = 0; ni < NI; ni++)
                    mma16816(acc[mi][ni], afl[mi], bf[ni >> 1][(ni & 1) * 2],
                             bf[ni >> 1][(ni & 1) * 2 + 1]);
            if (NCH == 3) {
                uint32_t bfl[NJ][4];
#pragma unroll
                for (int nj = 0; nj < NJ; nj++)
                    ldm4(bfl[nj], bL0 + (uint32_t)((bRow + nj * 16) * RS + bK + kk) * 2);
#pragma unroll
                for (int mi = 0; mi < 2; mi++)
#pragma unroll
                    for (int ni = 0; ni < NI; ni++)
                        mma16816(acc[mi][ni], afh[mi], bfl[ni >> 1][(ni & 1) * 2],
                                 bfl[ni >> 1][(ni & 1) * 2 + 1]);
            }
        }
        __syncthreads();
    }
#undef LOAD_STAGE

    // ---------------- epilogue ----------------
    const int gr0 = (int)am0 + wr * 32 + (lane >> 2);
    const int gc0 = (int)bn0 + wc * WN + (lane & 3) * 2;
#pragma unroll
    for (int mi = 0; mi < 2; mi++)
#pragma unroll
        for (int ni = 0; ni < NI; ni++) {
            const float* c = acc[mi][ni];
            const int col = gc0 + ni * 8;
#pragma unroll
            for (int hh = 0; hh < 2; hh++) {
                const int row = gr0 + mi * 16 + hh * 8;
                float v0 = c[hh * 2 + 0] * scale, v1 = c[hh * 2 + 1] * scale;
                if (ep == 0) {                      // tw: split h/l, ld 2048
                    long o = (long)row * 2048 + col;
                    H h0, l0, h1, l1;
                    hsplit(v0, h0, l0); hsplit(v1, h1, l1);
                    *(__half2*)(hp0 + o) = __halves2half2(h0, h1);
                    *(__half2*)(hp1 + o) = __halves2half2(l0, l1);
                } else if (ep == 1) {               // logits fp32 [z][l][s]
                    long o = (long)z * 16384 + (long)row * 256 + col;
                    float2 v = {v0, v1};
                    *(float2*)(fp0 + o) = v;
                } else if (ep == 2) {               // Yt: hi-only, ld 2048
                    long o = ((long)z * 64 + row) * 2048 + col;
                    *(__half2*)(hp0 + o) = __halves2half2(__float2half_rn(v0), __float2half_rn(v1));
                } else if (ep == 3) {               // img_cat: fp32 ic + hi scatter into xT
                    long o = (long)row * 4096 + col;
                    float2 v = {v0, v1};
                    *(float2*)(fp0 + o) = v;
                    hp0[(long)col * 2048 + 1024 + row] = __float2half_rn(v0);
                    hp0[(long)(col + 1) * 2048 + 1024 + row] = __float2half_rn(v1);
                } else {                            // ep4: conv gb fp32
                    long o = (long)row * 4096 + col;
                    float2 v = {v0, v1};
                    *(float2*)(fp0 + o) = v;
                }
            }
        }
}

// =====================================================================
// prep kernels
// =====================================================================
__global__ void p_text(const float* __restrict__ t) {
    for (long i = (long)blockIdx.x * blockDim.x + threadIdx.x; i < 64L * 64 * 1024;
         i += (long)gridDim.x * blockDim.x) {
        long row = i >> 10; int c = (int)(i & 1023);
        H h, l; hsplit(t[i], h, l);
        d_xth[row * 2048 + c] = h; d_xtl[row * 2048 + c] = l;
    }
}

__global__ void p_w(const float* __restrict__ w) {
    __shared__ float t[32][33];
    int o0 = blockIdx.y * 32, c0 = blockIdx.x * 32;
    int tx = threadIdx.x, ty = threadIdx.y;
#pragma unroll
    for (int j = 0; j < 4; j++) {
        int o = o0 + ty + j * 8;
        float v = w[(long)o * 2048 + c0 + tx] * WSCALE;
        H h, l; hsplit(v, h, l);
        d_wih[(long)o * 2048 + c0 + tx] = h;
        d_wil[(long)o * 2048 + c0 + tx] = l;
        t[ty + j * 8][tx] = v;
    }
    __syncthreads();
#pragma unroll
    for (int j = 0; j < 4; j++) {
        int c = c0 + ty + j * 8;
        float v = t[tx][ty + j * 8];
        H h, l; hsplit(v, h, l);
        d_wTh[(long)c * 1024 + o0 + tx] = h;
        d_wTl[(long)c * 1024 + o0 + tx] = l;
    }
}

__global__ void p_img(const float* __restrict__ img) {
    __shared__ float t[32][33];
    int n = blockIdx.z, c0 = blockIdx.y * 32, s0 = blockIdx.x * 32;
    int tx = threadIdx.x, ty = threadIdx.y;
    const float* ip = img + (long)n * 2048 * 256;
#pragma unroll
    for (int j = 0; j < 4; j++) {
        int c = c0 + ty + j * 8;
        float v = ip[(long)c * 256 + s0 + tx];
        d_imh[(long)n * 524288 + (long)c * 256 + s0 + tx] = __float2half_rn(v);
        t[ty + j * 8][tx] = v;
    }
    __syncthreads();
#pragma unroll
    for (int j = 0; j < 4; j++) {
        int s = s0 + ty + j * 8;
        float v = t[tx][ty + j * 8];
        H h, l; hsplit(v, h, l);
        long o = (long)n * 524288 + (long)s * 2048 + c0 + tx;
        d_iTh[o] = h; d_iTl[o] = l;
    }
}

__global__ void p_w1(const float* __restrict__ wg1, const float* __restrict__ wb1) {
    for (long i = (long)blockIdx.x * blockDim.x + threadIdx.x; i < 1024L * 2048;
         i += (long)gridDim.x * blockDim.x) {
        float v = ((i < 512L * 2048) ? wg1[i] : wb1[i - 512L * 2048]) * WSCALE;
        hsplit(v, d_w1h[i], d_w1l[i]);
    }
}
__global__ void p_w3(const float* __restrict__ wg3, const float* __restrict__ wb3) {
    int row = blockIdx.x;
    const float* src = (row < 512) ? wg3 + (long)row * 6144 : wb3 + (long)(row - 512) * 6144;
    for (int c = threadIdx.x; c < 6144; c += 256) {
        float v = src[c] * WSCALE;
        hsplit(v, d_w3h[(long)row * 6144 + c], d_w3l[(long)row * 6144 + c]);
    }
}

__global__ void p_x3() {
    int row = blockIdx.x;                  // (n,l)
    int n = row >> 6, l = row & 63;
    for (int c = threadIdx.x; c < 2048; c += 256) {
#pragma unroll
        for (int t = 0; t < 3; t++) {
            int sl = l + t - 1;
            H vh = __float2half_rn(0.f);
            if (sl >= 0 && sl < 64) vh = d_xth[((long)(n << 6) + sl) * 2048 + c];
            d_x3h[(long)row * 6144 + (long)c * 3 + t] = vh;
        }
    }
}

__global__ void k_softmax(float* __restrict__ d_attn) {
    int warp = threadIdx.x >> 5, lane = threadIdx.x & 31;
    int row = blockIdx.x * 8 + warp;
    float* lg = g_lg + (long)row * 256;
    float v[8];
    float m = -1e30f;
#pragma unroll
    for (int j = 0; j < 8; j++) { v[j] = lg[lane + j * 32]; m = fmaxf(m, v[j]); }
#pragma unroll
    for (int o = 16; o; o >>= 1) m = fmaxf(m, __shfl_xor_sync(0xffffffffu, m, o));
    float s = 0.f;
#pragma unroll
    for (int j = 0; j < 8; j++) { v[j] = __expf(v[j] - m); s += v[j]; }
#pragma unroll
    for (int o = 16; o; o >>= 1) s += __shfl_xor_sync(0xffffffffu, s, o);
    float inv = 1.f / s;
#pragma unroll
    for (int j = 0; j < 8; j++) {
        float a = v[j] * inv;
        int idx = lane + j * 32;
        d_attn[(long)row * 256 + idx] = a;
        H h, l; hsplit(a, h, l);
        d_ath[(long)row * 256 + idx] = h;
        d_atl[(long)row * 256 + idx] = l;
    }
}

__global__ void k_film(const float* __restrict__ bg1, const float* __restrict__ bb1,
                       const float* __restrict__ bg3, const float* __restrict__ bb3,
                       float* __restrict__ out) {
    for (long idx = (long)blockIdx.x * blockDim.x + threadIdx.x; idx < 64L * 1024 * 64;
         idx += (long)gridDim.x * blockDim.x) {
        int l = (int)(idx & 63), co = (int)((idx >> 6) & 1023), n = (int)(idx >> 16);
        long cnl = (long)(n << 6) + l;
        float g, b;
        if (co < 512) {
            g = g_gb1[(long)co * 4096 + cnl] + bg1[co];
            b = g_gb1[(long)(co + 512) * 4096 + cnl] + bb1[co];
        } else {
            int c2 = co - 512;
            g = g_gb3[(long)c2 * 4096 + cnl] + bg3[c2];
            b = g_gb3[(long)(c2 + 512) * 4096 + cnl] + bb3[c2];
        }
        out[idx] = g * g_ic[(long)co * 4096 + cnl] + b;
    }
}

// =====================================================================
extern "C" void kernel_launch(void* const* d_in, const int* in_sizes, int n_in,
                              void* d_out, int out_size) {
    const float* img   = (const float*)d_in[0];
    const float* text  = (const float*)d_in[1];
    const float* w_img = (const float*)d_in[2];
    const float* wg1   = (const float*)d_in[3];
    const float* bg1   = (const float*)d_in[4];
    const float* wg3   = (const float*)d_in[5];
    const float* bg3   = (const float*)d_in[6];
    const float* wb1   = (const float*)d_in[7];
    const float* bb1   = (const float*)d_in[8];
    const float* wb3   = (const float*)d_in[9];
    const float* bb3   = (const float*)d_in[10];

    float* out = (float*)d_out;                               // [64,1024,64]
    float* attn_out = out + 64L * 1024 * 64;                  // [64,64,256]

    H *xth, *xtl, *wTh, *wTl, *wih, *wil, *w1h, *w1l, *w3h, *w3l;
    H *twh, *twl, *imh, *iTh, *iTl, *ath, *atl, *yth, *x3h;
    float *lg, *ic, *gb1, *gb3;
    cudaGetSymbolAddress((void**)&xth, d_xth);  cudaGetSymbolAddress((void**)&xtl, d_xtl);
    cudaGetSymbolAddress((void**)&wTh, d_wTh);  cudaGetSymbolAddress((void**)&wTl, d_wTl);
    cudaGetSymbolAddress((void**)&wih, d_wih);  cudaGetSymbolAddress((void**)&wil, d_wil);
    cudaGetSymbolAddress((void**)&w1h, d_w1h);  cudaGetSymbolAddress((void**)&w1l, d_w1l);
    cudaGetSymbolAddress((void**)&w3h, d_w3h);  cudaGetSymbolAddress((void**)&w3l, d_w3l);
    cudaGetSymbolAddress((void**)&twh, d_twh);  cudaGetSymbolAddress((void**)&twl, d_twl);
    cudaGetSymbolAddress((void**)&imh, d_imh);
    cudaGetSymbolAddress((void**)&iTh, d_iTh);  cudaGetSymbolAddress((void**)&iTl, d_iTl);
    cudaGetSymbolAddress((void**)&ath, d_ath);  cudaGetSymbolAddress((void**)&atl, d_atl);
    cudaGetSymbolAddress((void**)&yth, d_yth);
    cudaGetSymbolAddress((void**)&x3h, d_x3h);
    cudaGetSymbolAddress((void**)&lg, g_lg);    cudaGetSymbolAddress((void**)&ic, g_ic);
    cudaGetSymbolAddress((void**)&gb1, g_gb1);  cudaGetSymbolAddress((void**)&gb3, g_gb3);

    const int SM_B3 = 122880;   // <128,128,3>
    const int SM_B2 = 92160;    // <128,128,2>
    const int SM_S3 = 61440;    // <64,64,3>
    const int SM_S2 = 46080;    // <64,64,2>
    cudaFuncSetAttribute(k_gemm<128, 128, 3>, cudaFuncAttributeMaxDynamicSharedMemorySize, SM_B3);
    cudaFuncSetAttribute(k_gemm<128, 128, 2>, cudaFuncAttributeMaxDynamicSharedMemorySize, SM_B2);
    cudaFuncSetAttribute(k_gemm<64, 64, 3>, cudaFuncAttributeMaxDynamicSharedMemorySize, SM_S3);
    cudaFuncSetAttribute(k_gemm<64, 64, 2>, cudaFuncAttributeMaxDynamicSharedMemorySize, SM_S2);

    // ---- preps ----
    p_text<<<2048, 256>>>(text);
    p_w   <<<dim3(64, 32), dim3(32, 8)>>>(w_img);
    p_img <<<dim3(8, 64, 64), dim3(32, 8)>>>(img);
    p_w1  <<<2048, 256>>>(wg1, wb1);
    p_w3  <<<1024, 256>>>(wg3, wb3);

    // ---- tw: M=4096 N=2048 K=1024, 3-chain ----
    k_gemm<128, 128, 3><<<dim3(16, 32, 1), 256, SM_B3>>>(
        xth, xtl, 0, wTh, wTl, 0, 1024, 2048, 1024, 0, T_INV * WINV, nullptr, twh, twl);

    // ---- logits: batched M=64 N=256 K=2048, 3-chain ----
    k_gemm<64, 64, 3><<<dim3(4, 1, 64), 128, SM_S3>>>(
        twh, twl, 64L * 2048, iTh, iTl, 256L * 2048, 2048, 2048, 2048, 1, 1.0f, lg, nullptr, nullptr);

    k_softmax<<<512, 256>>>(attn_out);

    // ---- Yt: batched M=64 N=2048 K=256, 2-chain (A=attn exact, B=img fp16) ----
    k_gemm<64, 64, 2><<<dim3(32, 1, 64), 128, SM_S2>>>(
        ath, atl, 64L * 256, imh, nullptr, 2048L * 256, 256, 256, 256, 2, 1.0f, nullptr, yth, nullptr);

    // ---- img_cat: M=1024 N=4096 K=2048, 2-chain (A=w exact, B=Yt fp16) ----
    k_gemm<128, 128, 2><<<dim3(32, 8, 1), 256, SM_B2>>>(
        wih, wil, 0, yth, nullptr, 0, 2048, 2048, 2048, 3, WINV, ic, xth, nullptr);

    p_x3<<<4096, 256>>>();

    // ---- conv1: M=1024 N=4096 K=2048, 2-chain ----
    k_gemm<128, 128, 2><<<dim3(32, 8, 1), 256, SM_B2>>>(
        w1h, w1l, 0, xth, nullptr, 0, 2048, 2048, 2048, 4, WINV, gb1, nullptr, nullptr);

    // ---- conv3: M=1024 N=4096 K=6144, 2-chain ----
    k_gemm<128, 128, 2><<<dim3(32, 8, 1), 256, SM_B2>>>(
        w3h, w3l, 0, x3h, nullptr, 0, 6144, 6144, 6144, 4, WINV, gb3, nullptr, nullptr);

    k_film<<<4096, 256>>>(bg1, bb1, bg3, bb3, out);
}